// round 2
// baseline (speedup 1.0000x reference)
#include <cuda_runtime.h>
#include <string.h>

#define BATCH    32
#define CIN      192
#define T_FRAMES 8192
#define H        192
#define NPH      1024
#define NOUT     4
#define EPS      1e-5f

// ---------------- device scratch (no allocations allowed) ----------------
__device__ int   g_ends[BATCH * NPH];
__device__ float g_spec[BATCH * H * NPH];
__device__ float g_h0  [BATCH * H * NPH];
__device__ float g_a0  [BATCH * H * NPH];

// ---------------- packed fp32x2 FMA (Blackwell FFMA2) ----------------
__device__ __forceinline__ float2 ffma2(float2 a, float2 b, float2 c) {
    unsigned long long ua, ub, uc, ud;
    memcpy(&ua, &a, 8); memcpy(&ub, &b, 8); memcpy(&uc, &c, 8);
    asm("fma.rn.f32x2 %0, %1, %2, %3;" : "=l"(ud) : "l"(ua), "l"(ub), "l"(uc));
    float2 d; memcpy(&d, &ud, 8);
    return d;
}

// ---------------- 1) per-batch inclusive scan of durations ----------------
__global__ void k_cumsum(const int* __restrict__ w) {
    __shared__ int s[NPH];
    int b = blockIdx.x, t = threadIdx.x;
    s[t] = w[b * NPH + t];
    __syncthreads();
    for (int off = 1; off < NPH; off <<= 1) {
        int v = (t >= off) ? s[t - off] : 0;
        __syncthreads();
        s[t] += v;
        __syncthreads();
    }
    g_ends[b * NPH + t] = s[t];
}

// ---------------- 2) segment mean: x[B,C,T] -> spec[B,C,NPH] ----------------
#define SEG_J 8
__global__ void k_segmean(const float* __restrict__ x) {
    __shared__ float fr[CIN][SEG_J * 7 + 1];   // max 56 frames per 8-phoneme tile
    __shared__ int se[SEG_J + 1];
    int b = blockIdx.y;
    int j0 = blockIdx.x * SEG_J;
    int tid = threadIdx.x;
    if (tid <= SEG_J) {
        int j = j0 + tid - 1;
        se[tid] = (j >= 0) ? g_ends[b * NPH + j] : 0;
    }
    __syncthreads();
    int t0 = se[0];
    int L  = se[SEG_J] - t0;                    // frames covered by this tile (<=56)
    const float* xb = x + (size_t)b * CIN * T_FRAMES + t0;
    for (int idx = tid; idx < CIN * L; idx += blockDim.x) {
        int c = idx / L, tt = idx - c * L;
        fr[c][tt] = xb[c * T_FRAMES + tt];
    }
    __syncthreads();
    for (int idx = tid; idx < CIN * SEG_J; idx += blockDim.x) {
        int c = idx >> 3, jj = idx & 7;
        int s = se[jj] - t0, e = se[jj + 1] - t0;
        float acc = 0.f;
        for (int tt = s; tt < e; ++tt) acc += fr[c][tt];
        g_spec[(b * CIN + c) * NPH + j0 + jj] = (e > s) ? acc / (float)(e - s) : 0.f;
    }
}

// ---------------- 3) fused GEMM / conv3 + bias + mask + relu + LN (+linear) ----------------
// MODE 0: KSZ=1  spec -> h0 (pre projection + bias, no activation)
// MODE 1: KSZ=3  h0*m -> conv0+b, relu(*m), LN0(*m in), *m -> a0
// MODE 2: KSZ=3  a0*m -> conv1+b, relu(*m), LN1(*m in), *m -> linear -> *m -> out
#define JT   64
#define CK   24
#define CKP  25
#define IPAD 68
#define CONV_THREADS 256
#define CONV_SMEM (H * CKP * (int)sizeof(float2) + H * IPAD * (int)sizeof(float))  // 90624

template <int KSZ, int MODE>
__global__ void __launch_bounds__(CONV_THREADS)
k_conv(const float* __restrict__ W, const float* __restrict__ bias,
       const float* __restrict__ xmask,
       const float* __restrict__ lng, const float* __restrict__ lnb,
       const float* __restrict__ linw, const float* __restrict__ linb,
       float* __restrict__ outp) {
    extern __shared__ char smem[];
    float2* ws2 = (float2*)smem;                                  // [H][CKP] duplicated weights
    float*  ins = (float*)(smem + H * CKP * sizeof(float2));      // [H][IPAD] input tile
    // epilogue aliases (used only after a sync, main-loop smem is dead by then)
    float* red1 = (float*)smem;           // [64][33]
    float* red2 = red1 + 64 * 33;         // [64][33]
    float* redL = red2 + 64 * 33;         // [4][64][33]

    const int b   = blockIdx.y;
    const int j0  = blockIdx.x * JT;
    const int tid = threadIdx.x;
    const int jg  = tid & 7;        // 8 j-groups
    const int ocg = tid >> 3;       // 32 oc-groups
    const int oc0 = ocg * 6;
    const int jb  = jg * 8;
    const int TILE_IN = JT + KSZ - 1;
    const int HALO    = (KSZ - 1) / 2;

    const float* inbuf = (MODE == 0) ? g_spec : ((MODE == 1) ? g_h0 : g_a0);

    // --- load input tile (coalesced per channel row), premask for conv stages ---
    for (int idx = tid; idx < H * TILE_IN; idx += CONV_THREADS) {
        int c = idx / TILE_IN, col = idx - c * TILE_IN;
        int j = j0 + col - HALO;
        float v = 0.f;
        if (j >= 0 && j < NPH) {
            v = inbuf[(b * H + c) * NPH + j];
            if (MODE != 0) v *= xmask[b * NPH + j];
        }
        ins[c * IPAD + col] = v;
    }

    float2 acc[6][4];
#pragma unroll
    for (int u = 0; u < 6; u++)
#pragma unroll
        for (int v = 0; v < 4; v++) acc[u][v] = make_float2(0.f, 0.f);

    const int KTOT = H * KSZ;
    for (int kb = 0; kb < KTOT; kb += CK) {
        __syncthreads();
        // stage weight chunk, duplicated for packed FMA
        for (int idx = tid; idx < H * CK; idx += CONV_THREADS) {
            int oc = idx / CK, kk = idx - oc * CK;
            float wv = W[oc * KTOT + kb + kk];
            ws2[oc * CKP + kk] = make_float2(wv, wv);
        }
        __syncthreads();

        if (KSZ == 3) {
#pragma unroll
            for (int icl = 0; icl < CK / 3; ++icl) {
                int ic = kb / 3 + icl;
                const float2* ip = (const float2*)&ins[ic * IPAD + jb];
                float2 a0 = ip[0], a1 = ip[1], a2 = ip[2], a3 = ip[3], a4 = ip[4];
                float2 m0 = make_float2(a0.y, a1.x);
                float2 m1 = make_float2(a1.y, a2.x);
                float2 m2 = make_float2(a2.y, a3.x);
                float2 m3 = make_float2(a3.y, a4.x);
#pragma unroll
                for (int u = 0; u < 6; u++) {
                    float2 w0 = ws2[(oc0 + u) * CKP + icl * 3 + 0];
                    float2 w1 = ws2[(oc0 + u) * CKP + icl * 3 + 1];
                    float2 w2 = ws2[(oc0 + u) * CKP + icl * 3 + 2];
                    acc[u][0] = ffma2(w0, a0, acc[u][0]);
                    acc[u][0] = ffma2(w1, m0, acc[u][0]);
                    acc[u][0] = ffma2(w2, a1, acc[u][0]);
                    acc[u][1] = ffma2(w0, a1, acc[u][1]);
                    acc[u][1] = ffma2(w1, m1, acc[u][1]);
                    acc[u][1] = ffma2(w2, a2, acc[u][1]);
                    acc[u][2] = ffma2(w0, a2, acc[u][2]);
                    acc[u][2] = ffma2(w1, m2, acc[u][2]);
                    acc[u][2] = ffma2(w2, a3, acc[u][2]);
                    acc[u][3] = ffma2(w0, a3, acc[u][3]);
                    acc[u][3] = ffma2(w1, m3, acc[u][3]);
                    acc[u][3] = ffma2(w2, a4, acc[u][3]);
                }
            }
        } else {
#pragma unroll
            for (int kk = 0; kk < CK; ++kk) {
                int ic = kb + kk;
                const float2* ip = (const float2*)&ins[ic * IPAD + jb];
                float2 a0 = ip[0], a1 = ip[1], a2 = ip[2], a3 = ip[3];
#pragma unroll
                for (int u = 0; u < 6; u++) {
                    float2 wv = ws2[(oc0 + u) * CKP + kk];
                    acc[u][0] = ffma2(wv, a0, acc[u][0]);
                    acc[u][1] = ffma2(wv, a1, acc[u][1]);
                    acc[u][2] = ffma2(wv, a2, acc[u][2]);
                    acc[u][3] = ffma2(wv, a3, acc[u][3]);
                }
            }
        }
    }

    float bv[6];
#pragma unroll
    for (int u = 0; u < 6; u++) bv[u] = __ldg(&bias[oc0 + u]);

    if (MODE == 0) {
#pragma unroll
        for (int u = 0; u < 6; u++) {
            float* op = &g_h0[(b * H + oc0 + u) * NPH + j0 + jb];
#pragma unroll
            for (int v = 0; v < 4; v++) {
                op[2 * v]     = acc[u][v].x + bv[u];
                op[2 * v + 1] = acc[u][v].y + bv[u];
            }
        }
        return;
    }

    // ---- conv stages: bias, mask, relu, mask, LN ----
    float mj[8];
#pragma unroll
    for (int vv = 0; vv < 8; vv++) mj[vv] = xmask[b * NPH + j0 + jb + vv];

    float val[6][8];
#pragma unroll
    for (int u = 0; u < 6; u++) {
#pragma unroll
        for (int v = 0; v < 4; v++) {
            float t0 = (acc[u][v].x + bv[u]) * mj[2 * v];
            float t1 = (acc[u][v].y + bv[u]) * mj[2 * v + 1];
            val[u][2 * v]     = fmaxf(t0, 0.f) * mj[2 * v];
            val[u][2 * v + 1] = fmaxf(t1, 0.f) * mj[2 * v + 1];
        }
    }
    __syncthreads();   // main-loop smem dead; reuse for reductions
#pragma unroll
    for (int vv = 0; vv < 8; vv++) {
        float s1 = 0.f, s2 = 0.f;
#pragma unroll
        for (int u = 0; u < 6; u++) { s1 += val[u][vv]; s2 += val[u][vv] * val[u][vv]; }
        red1[(jb + vv) * 33 + ocg] = s1;
        red2[(jb + vv) * 33 + ocg] = s2;
    }
    __syncthreads();
    float mean[8], rstd[8];
#pragma unroll
    for (int vv = 0; vv < 8; vv++) {
        float s1 = 0.f, s2 = 0.f;
#pragma unroll
        for (int i = 0; i < 32; i++) { s1 += red1[(jb + vv) * 33 + i]; s2 += red2[(jb + vv) * 33 + i]; }
        float m  = s1 * (1.f / H);
        float vr = s2 * (1.f / H) - m * m;
        mean[vv] = m;
        rstd[vv] = rsqrtf(vr + EPS);
    }

    if (MODE == 1) {
#pragma unroll
        for (int u = 0; u < 6; u++) {
            float ga = __ldg(&lng[oc0 + u]), bb = __ldg(&lnb[oc0 + u]);
            float* op = &g_a0[(b * H + oc0 + u) * NPH + j0 + jb];
#pragma unroll
            for (int vv = 0; vv < 8; vv++) {
                float ln = (val[u][vv] - mean[vv]) * rstd[vv] * ga + bb;
                op[vv] = ln * mj[vv];
            }
        }
    } else {
        float lp[4][8];
#pragma unroll
        for (int o = 0; o < 4; o++)
#pragma unroll
            for (int vv = 0; vv < 8; vv++) lp[o][vv] = 0.f;
#pragma unroll
        for (int u = 0; u < 6; u++) {
            float ga = __ldg(&lng[oc0 + u]), bb = __ldg(&lnb[oc0 + u]);
            float wl[4];
#pragma unroll
            for (int o = 0; o < 4; o++) wl[o] = __ldg(&linw[o * H + oc0 + u]);
#pragma unroll
            for (int vv = 0; vv < 8; vv++) {
                float ln = ((val[u][vv] - mean[vv]) * rstd[vv] * ga + bb) * mj[vv];
#pragma unroll
                for (int o = 0; o < 4; o++) lp[o][vv] += ln * wl[o];
            }
        }
#pragma unroll
        for (int o = 0; o < 4; o++)
#pragma unroll
            for (int vv = 0; vv < 8; vv++)
                redL[(o * 64 + jb + vv) * 33 + ocg] = lp[o][vv];
        __syncthreads();
        {
            int o = tid >> 6, jt = tid & 63;
            float s = 0.f;
#pragma unroll
            for (int i = 0; i < 32; i++) s += redL[(o * 64 + jt) * 33 + i];
            s += __ldg(&linb[o]);
            s *= xmask[b * NPH + j0 + jt];
            outp[(b * NOUT + o) * NPH + j0 + jt] = s;
        }
    }
}

// ---------------- launch ----------------
extern "C" void kernel_launch(void* const* d_in, const int* in_sizes, int n_in,
                              void* d_out, int out_size) {
    (void)in_sizes; (void)n_in; (void)out_size;
    const float* x    = (const float*)d_in[0];
    const float* xm   = (const float*)d_in[1];
    const int*   w    = (const int*)d_in[2];
    const float* prew = (const float*)d_in[3];
    const float* preb = (const float*)d_in[4];
    const float* c0w  = (const float*)d_in[5];
    const float* c0b  = (const float*)d_in[6];
    const float* g0   = (const float*)d_in[7];
    const float* b0   = (const float*)d_in[8];
    const float* c1w  = (const float*)d_in[9];
    const float* c1b  = (const float*)d_in[10];
    const float* g1   = (const float*)d_in[11];
    const float* b1   = (const float*)d_in[12];
    const float* lw   = (const float*)d_in[13];
    const float* lb   = (const float*)d_in[14];
    float* out = (float*)d_out;

    cudaFuncSetAttribute((const void*)k_conv<1, 0>, cudaFuncAttributeMaxDynamicSharedMemorySize, CONV_SMEM);
    cudaFuncSetAttribute((const void*)k_conv<3, 1>, cudaFuncAttributeMaxDynamicSharedMemorySize, CONV_SMEM);
    cudaFuncSetAttribute((const void*)k_conv<3, 2>, cudaFuncAttributeMaxDynamicSharedMemorySize, CONV_SMEM);

    k_cumsum<<<BATCH, NPH>>>(w);
    k_segmean<<<dim3(NPH / SEG_J, BATCH), 256>>>(x);
    dim3 cg(NPH / JT, BATCH);
    k_conv<1, 0><<<cg, CONV_THREADS, CONV_SMEM>>>(prew, preb, xm, nullptr, nullptr, nullptr, nullptr, nullptr);
    k_conv<3, 1><<<cg, CONV_THREADS, CONV_SMEM>>>(c0w, c0b, xm, g0, b0, nullptr, nullptr, nullptr);
    k_conv<3, 2><<<cg, CONV_THREADS, CONV_SMEM>>>(c1w, c1b, xm, g1, b1, lw, lb, out);
}

// round 4
// speedup vs baseline: 2.6094x; 2.6094x over previous
#include <cuda_runtime.h>
#include <cuda_bf16.h>
#include <cstdint>

#define BATCH    32
#define CIN      192
#define T_FRAMES 8192
#define H        192
#define NPH      1024
#define NOUT     4
#define EPS      1e-5f

#define JT 128

// ---- smem layout (bytes) ----
#define SM_PAR 0          // bias[192], gamma[192], beta[192], linw[768], linb[4] = 1348 f
#define SM_AH  5504       // A hi plane: 128 rows x 36 u32 (72 bf16, 144B stride)
#define SM_AL  23936
#define SM_BH  42368      // B hi plane: 192 rows x 36 u32
#define SM_BL  70016
#define SMEM_BYTES 97664

// ---- device scratch ----
#define PLANE (BATCH * NPH * H)
__device__ __align__(16) int g_ends[BATCH * NPH];
__device__ __align__(16) __nv_bfloat16 g_spec_h[PLANE], g_spec_l[PLANE];
__device__ __align__(16) __nv_bfloat16 g_h0_h[PLANE],   g_h0_l[PLANE];
__device__ __align__(16) __nv_bfloat16 g_a0_h[PLANE],   g_a0_l[PLANE];
#define WTOT (21 * 12288)   // 3 chunks pre + 9 conv0 + 9 conv1, each 192x64
__device__ __align__(16) __nv_bfloat16 g_w_h[WTOT], g_w_l[WTOT];

// ===================== helpers =====================
__device__ __forceinline__ uint32_t smem_u32(const void* p) {
    uint32_t a;
    asm("{ .reg .u64 t; cvta.to.shared.u64 t, %1; cvt.u32.u64 %0, t; }" : "=r"(a) : "l"(p));
    return a;
}
__device__ __forceinline__ void ldsm4(uint32_t* r, uint32_t a) {
    asm volatile("ldmatrix.sync.aligned.m8n8.x4.shared.b16 {%0,%1,%2,%3}, [%4];"
        : "=r"(r[0]), "=r"(r[1]), "=r"(r[2]), "=r"(r[3]) : "r"(a));
}
__device__ __forceinline__ void ldsm2(uint32_t* r, uint32_t a) {
    asm volatile("ldmatrix.sync.aligned.m8n8.x2.shared.b16 {%0,%1}, [%2];"
        : "=r"(r[0]), "=r"(r[1]) : "r"(a));
}
__device__ __forceinline__ void mma16816(float* d, const uint32_t* a, const uint32_t* bq) {
    asm volatile("mma.sync.aligned.m16n8k16.row.col.f32.bf16.bf16.f32 "
        "{%0,%1,%2,%3}, {%4,%5,%6,%7}, {%8,%9}, {%0,%1,%2,%3};"
        : "+f"(d[0]), "+f"(d[1]), "+f"(d[2]), "+f"(d[3])
        : "r"(a[0]), "r"(a[1]), "r"(a[2]), "r"(a[3]), "r"(bq[0]), "r"(bq[1]));
}
__device__ __forceinline__ uint32_t pack_bf16(float hi_el, float lo_el) { // lo 16 bits = bf16(lo_el)
    uint32_t r;
    asm("cvt.rn.bf16x2.f32 %0, %1, %2;" : "=r"(r) : "f"(hi_el), "f"(lo_el));
    return r;
}

// ===================== 0) weight prep: split + im2col chunk reorder =====================
__global__ void k_prep_w(const float* __restrict__ prew, const float* __restrict__ c0w,
                         const float* __restrict__ c1w) {
    for (int idx = blockIdx.x * blockDim.x + threadIdx.x; idx < WTOT; idx += gridDim.x * blockDim.x) {
        int chunk = idx / 12288, rem = idx % 12288;
        int oc = rem >> 6, i = rem & 63;
        float v;
        if (chunk < 3) {
            v = prew[oc * CIN + chunk * 64 + i];
        } else if (chunk < 12) {
            int cc = chunk - 3, tau = cc / 3, ic = (cc % 3) * 64 + i;
            v = c0w[(oc * H + ic) * 3 + tau];
        } else {
            int cc = chunk - 12, tau = cc / 3, ic = (cc % 3) * 64 + i;
            v = c1w[(oc * H + ic) * 3 + tau];
        }
        __nv_bfloat16 hb = __float2bfloat16(v);
        g_w_h[idx] = hb;
        g_w_l[idx] = __float2bfloat16(v - __bfloat162float(hb));
    }
}

// ===================== 1) per-batch inclusive scan =====================
__global__ void k_cumsum(const int* __restrict__ w) {
    __shared__ int s[NPH];
    int b = blockIdx.x, t = threadIdx.x;
    s[t] = w[b * NPH + t];
    __syncthreads();
    for (int off = 1; off < NPH; off <<= 1) {
        int v = (t >= off) ? s[t - off] : 0;
        __syncthreads();
        s[t] += v;
        __syncthreads();
    }
    g_ends[b * NPH + t] = s[t];
}

// ===================== 2) segment mean -> bf16 hi/lo planes [b][j][c] =====================
#define SEG_J 8
__global__ void k_segmean(const float* __restrict__ x) {
    __shared__ float fr[CIN][SEG_J * 7 + 1];
    __shared__ int se[SEG_J + 1];
    int b = blockIdx.y, j0 = blockIdx.x * SEG_J, tid = threadIdx.x;
    if (tid <= SEG_J) {
        int j = j0 + tid - 1;
        se[tid] = (j >= 0) ? g_ends[b * NPH + j] : 0;
    }
    __syncthreads();
    int t0 = se[0], L = se[SEG_J] - t0;
    const float* xb = x + (size_t)b * CIN * T_FRAMES + t0;
    for (int idx = tid; idx < CIN * L; idx += blockDim.x) {
        int c = idx / L, tt = idx - c * L;
        fr[c][tt] = xb[c * T_FRAMES + tt];
    }
    __syncthreads();
    for (int idx = tid; idx < CIN * SEG_J; idx += blockDim.x) {
        int c = idx >> 3, jj = idx & 7;
        int s = se[jj] - t0, e = se[jj + 1] - t0;
        float acc = 0.f;
        for (int tt = s; tt < e; ++tt) acc += fr[c][tt];
        float v = (e > s) ? acc / (float)(e - s) : 0.f;
        int o = (b * NPH + j0 + jj) * H + c;
        __nv_bfloat16 hb = __float2bfloat16(v);
        g_spec_h[o] = hb;
        g_spec_l[o] = __float2bfloat16(v - __bfloat162float(hb));
    }
}

// ===================== 3) fused HMMA GEMM layer =====================
// MODE 0: pre (K=192): (D+bias)*m -> h0 planes
// MODE 1: conv0 (K=576): relu((D+b)*m)*m -> LN -> *m*m -> a0 planes
// MODE 2: conv1: ... -> LN -> *m -> linear(4) + lb -> *m -> out
template <int NCHUNKS, int NTAPS, int MODE>
__global__ void __launch_bounds__(256, 1)
k_fused(const float* __restrict__ bias_g, const float* __restrict__ xmask,
        const float* __restrict__ lng, const float* __restrict__ lnb,
        const float* __restrict__ linw, const float* __restrict__ linb,
        int wofs, float* __restrict__ outp) {
    extern __shared__ char smem[];
    const uint32_t sb = smem_u32(smem);
    const int tid  = threadIdx.x;
    const int lane = tid & 31;
    const int wid  = tid >> 5;
    const int wm   = wid >> 2;   // 0..1  (m 64-half)
    const int wn   = wid & 3;    // 0..3  (n 48-quarter)
    const int b    = blockIdx.y;
    const int j0   = blockIdx.x * JT;

    const uint32_t* inH = (const uint32_t*)(MODE == 0 ? g_spec_h : (MODE == 1 ? g_h0_h : g_a0_h));
    const uint32_t* inL = (const uint32_t*)(MODE == 0 ? g_spec_l : (MODE == 1 ? g_h0_l : g_a0_l));
    uint32_t* outH = (uint32_t*)(MODE == 0 ? g_h0_h : g_a0_h);
    uint32_t* outL = (uint32_t*)(MODE == 0 ? g_h0_l : g_a0_l);
    const uint32_t* wH = ((const uint32_t*)g_w_h) + (wofs >> 1);
    const uint32_t* wL = ((const uint32_t*)g_w_l) + (wofs >> 1);

    float* par = (float*)(smem + SM_PAR);
    for (int i = tid; i < H; i += 256) par[i] = bias_g[i];
    if (MODE != 0)
        for (int i = tid; i < H; i += 256) { par[192 + i] = lng[i]; par[384 + i] = lnb[i]; }
    if (MODE == 2) {
        for (int i = tid; i < NOUT * H; i += 256) par[576 + i] = linw[i];
        if (tid < NOUT) par[1344 + tid] = linb[tid];
    }

    float acc[4][6][4];
#pragma unroll
    for (int mt = 0; mt < 4; mt++)
#pragma unroll
        for (int nt = 0; nt < 6; nt++)
#pragma unroll
            for (int q = 0; q < 4; q++) acc[mt][nt][q] = 0.f;

#pragma unroll 1
    for (int c = 0; c < NCHUNKS; c++) {
        const int tau = (NTAPS == 3) ? c / 3 : 0;
        const int icb = (NTAPS == 3) ? c % 3 : c;
        __syncthreads();
        // stage A: 128 rows x 32 u32 per plane
#pragma unroll
        for (int i = 0; i < 16; i++) {
            int idx = tid + i * 256;
            int r = idx >> 5, col = idx & 31;
            int jr = j0 + r + ((NTAPS == 3) ? tau - 1 : 0);
            uint32_t vh = 0, vl = 0;
            if ((unsigned)jr < NPH) {
                int s = (b * NPH + jr) * 96 + icb * 32 + col;
                vh = inH[s]; vl = inL[s];
            }
            ((uint32_t*)(smem + SM_AH))[r * 36 + col] = vh;
            ((uint32_t*)(smem + SM_AL))[r * 36 + col] = vl;
        }
        // stage B: 192 rows x 32 u32 per plane
#pragma unroll
        for (int i = 0; i < 24; i++) {
            int idx = tid + i * 256;
            int r = idx >> 5, col = idx & 31;
            int s = c * 6144 + idx;
            ((uint32_t*)(smem + SM_BH))[r * 36 + col] = wH[s];
            ((uint32_t*)(smem + SM_BL))[r * 36 + col] = wL[s];
        }
        __syncthreads();

#pragma unroll 1
        for (int ks = 0; ks < 4; ks++) {
            uint32_t ah[4][4], al[4][4], bh[6][2], bl[6][2];
            {
                int t = lane >> 3, r = lane & 7;
                int rowA = 64 * wm + r + ((t & 1) << 3);
                int colA = (ks << 4) + ((t & 2) << 2);
                uint32_t aoff = (uint32_t)(rowA * 144 + colA * 2);
#pragma unroll
                for (int mt = 0; mt < 4; mt++) {
                    ldsm4(ah[mt], sb + SM_AH + aoff + mt * (16 * 144));
                    ldsm4(al[mt], sb + SM_AL + aoff + mt * (16 * 144));
                }
                int tb = (lane >> 3) & 1, rb = lane & 7;
                int rowB = 48 * wn + rb;
                int colB = (ks << 4) + (tb << 3);
                uint32_t boff = (uint32_t)(rowB * 144 + colB * 2);
#pragma unroll
                for (int nt = 0; nt < 6; nt++) {
                    ldsm2(bh[nt], sb + SM_BH + boff + nt * (8 * 144));
                    ldsm2(bl[nt], sb + SM_BL + boff + nt * (8 * 144));
                }
            }
#pragma unroll
            for (int mt = 0; mt < 4; mt++)
#pragma unroll
                for (int nt = 0; nt < 6; nt++) {
                    mma16816(acc[mt][nt], ah[mt], bh[nt]);
                    mma16816(acc[mt][nt], ah[mt], bl[nt]);
                    mma16816(acc[mt][nt], al[mt], bh[nt]);
                }
        }
    }
    __syncthreads();   // smem (A/B stage) dead; safe to overlay reductions

    if (MODE == 0) {
#pragma unroll
        for (int mt = 0; mt < 4; mt++)
#pragma unroll
            for (int t = 0; t < 2; t++) {
                int jloc = 64 * wm + 16 * mt + (lane >> 2) + 8 * t;
                int j = j0 + jloc;
                float m = xmask[b * NPH + j];
                uint32_t* oH = outH + (b * NPH + j) * 96;
                uint32_t* oL = outL + (b * NPH + j) * 96;
#pragma unroll
                for (int nt = 0; nt < 6; nt++) {
                    int c0 = 48 * wn + 8 * nt + (lane & 3) * 2;
                    float v0 = (acc[mt][nt][2 * t + 0] + par[c0])     * m;
                    float v1 = (acc[mt][nt][2 * t + 1] + par[c0 + 1]) * m;
                    uint32_t ph = pack_bf16(v1, v0);
                    float f0 = __uint_as_float(ph << 16), f1 = __uint_as_float(ph & 0xffff0000u);
                    uint32_t pl = pack_bf16(v1 - f1, v0 - f0);
                    oH[c0 >> 1] = ph; oL[c0 >> 1] = pl;
                }
            }
        return;
    }

    float* redS1 = (float*)(smem + SM_AH);          // [128][4]
    float* redS2 = redS1 + 512;                     // [128][4]
    float* redLin = redS2 + 512;                    // [4][128][4]

    // pass 1: per-row masked relu sums
#pragma unroll
    for (int mt = 0; mt < 4; mt++)
#pragma unroll
        for (int t = 0; t < 2; t++) {
            int jloc = 64 * wm + 16 * mt + (lane >> 2) + 8 * t;
            float m = xmask[b * NPH + j0 + jloc];
            float s1 = 0.f, s2 = 0.f;
#pragma unroll
            for (int nt = 0; nt < 6; nt++) {
                int c0 = 48 * wn + 8 * nt + (lane & 3) * 2;
#pragma unroll
                for (int q = 0; q < 2; q++) {
                    float v = fmaxf((acc[mt][nt][2 * t + q] + par[c0 + q]) * m, 0.f) * m;
                    s1 += v; s2 += v * v;
                }
            }
            s1 += __shfl_xor_sync(0xffffffffu, s1, 1); s1 += __shfl_xor_sync(0xffffffffu, s1, 2);
            s2 += __shfl_xor_sync(0xffffffffu, s2, 1); s2 += __shfl_xor_sync(0xffffffffu, s2, 2);
            if ((lane & 3) == 0) { redS1[jloc * 4 + wn] = s1; redS2[jloc * 4 + wn] = s2; }
        }
    __syncthreads();

    // pass 2: normalize (+ linear head for MODE 2)
#pragma unroll
    for (int mt = 0; mt < 4; mt++)
#pragma unroll
        for (int t = 0; t < 2; t++) {
            int jloc = 64 * wm + 16 * mt + (lane >> 2) + 8 * t;
            int j = j0 + jloc;
            float m = xmask[b * NPH + j];
            float s1 = redS1[jloc * 4 + 0] + redS1[jloc * 4 + 1] + redS1[jloc * 4 + 2] + redS1[jloc * 4 + 3];
            float s2 = redS2[jloc * 4 + 0] + redS2[jloc * 4 + 1] + redS2[jloc * 4 + 2] + redS2[jloc * 4 + 3];
            float mean = s1 * (1.f / H);
            float rstd = rsqrtf(s2 * (1.f / H) - mean * mean + EPS);
            if (MODE == 1) {
                uint32_t* oH = outH + (b * NPH + j) * 96;
                uint32_t* oL = outL + (b * NPH + j) * 96;
#pragma unroll
                for (int nt = 0; nt < 6; nt++) {
                    int c0 = 48 * wn + 8 * nt + (lane & 3) * 2;
                    float v0 = fmaxf((acc[mt][nt][2 * t + 0] + par[c0])     * m, 0.f) * m;
                    float v1 = fmaxf((acc[mt][nt][2 * t + 1] + par[c0 + 1]) * m, 0.f) * m;
                    float y0 = ((v0 - mean) * rstd * par[192 + c0]     + par[384 + c0])     * m * m;
                    float y1 = ((v1 - mean) * rstd * par[192 + c0 + 1] + par[384 + c0 + 1]) * m * m;
                    uint32_t ph = pack_bf16(y1, y0);
                    float f0 = __uint_as_float(ph << 16), f1 = __uint_as_float(ph & 0xffff0000u);
                    uint32_t pl = pack_bf16(y1 - f1, y0 - f0);
                    oH[c0 >> 1] = ph; oL[c0 >> 1] = pl;
                }
            } else {
                float p0 = 0.f, p1 = 0.f, p2 = 0.f, p3 = 0.f;
#pragma unroll
                for (int nt = 0; nt < 6; nt++) {
                    int c0 = 48 * wn + 8 * nt + (lane & 3) * 2;
#pragma unroll
                    for (int q = 0; q < 2; q++) {
                        int cc = c0 + q;
                        float v = fmaxf((acc[mt][nt][2 * t + q] + par[cc]) * m, 0.f) * m;
                        float y = ((v - mean) * rstd * par[192 + cc] + par[384 + cc]) * m;
                        p0 += y * par[576 + 0 * H + cc];
                        p1 += y * par[576 + 1 * H + cc];
                        p2 += y * par[576 + 2 * H + cc];
                        p3 += y * par[576 + 3 * H + cc];
                    }
                }
                p0 += __shfl_xor_sync(0xffffffffu, p0, 1); p0 += __shfl_xor_sync(0xffffffffu, p0, 2);
                p1 += __shfl_xor_sync(0xffffffffu, p1, 1); p1 += __shfl_xor_sync(0xffffffffu, p1, 2);
                p2 += __shfl_xor_sync(0xffffffffu, p2, 1); p2 += __shfl_xor_sync(0xffffffffu, p2, 2);
                p3 += __shfl_xor_sync(0xffffffffu, p3, 1); p3 += __shfl_xor_sync(0xffffffffu, p3, 2);
                if ((lane & 3) == 0) {
                    redLin[(0 * 128 + jloc) * 4 + wn] = p0;
                    redLin[(1 * 128 + jloc) * 4 + wn] = p1;
                    redLin[(2 * 128 + jloc) * 4 + wn] = p2;
                    redLin[(3 * 128 + jloc) * 4 + wn] = p3;
                }
            }
        }

    if (MODE == 2) {
        __syncthreads();
        for (int oj = tid; oj < 512; oj += 256) {
            int o = oj >> 7, jl = oj & 127;
            float s = redLin[(o * 128 + jl) * 4 + 0] + redLin[(o * 128 + jl) * 4 + 1]
                    + redLin[(o * 128 + jl) * 4 + 2] + redLin[(o * 128 + jl) * 4 + 3];
            s += par[1344 + o];
            s *= xmask[b * NPH + j0 + jl];
            outp[(b * NOUT + o) * NPH + j0 + jl] = s;
        }
    }
}

// ===================== launch =====================
extern "C" void kernel_launch(void* const* d_in, const int* in_sizes, int n_in,
                              void* d_out, int out_size) {
    (void)in_sizes; (void)n_in; (void)out_size;
    const float* x    = (const float*)d_in[0];
    const float* xm   = (const float*)d_in[1];
    const int*   w    = (const int*)d_in[2];
    const float* prew = (const float*)d_in[3];
    const float* preb = (const float*)d_in[4];
    const float* c0w  = (const float*)d_in[5];
    const float* c0b  = (const float*)d_in[6];
    const float* g0   = (const float*)d_in[7];
    const float* b0   = (const float*)d_in[8];
    const float* c1w  = (const float*)d_in[9];
    const float* c1b  = (const float*)d_in[10];
    const float* g1   = (const float*)d_in[11];
    const float* b1   = (const float*)d_in[12];
    const float* lw   = (const float*)d_in[13];
    const float* lb   = (const float*)d_in[14];
    float* out = (float*)d_out;

    cudaFuncSetAttribute((const void*)k_fused<3, 1, 0>, cudaFuncAttributeMaxDynamicSharedMemorySize, SMEM_BYTES);
    cudaFuncSetAttribute((const void*)k_fused<9, 3, 1>, cudaFuncAttributeMaxDynamicSharedMemorySize, SMEM_BYTES);
    cudaFuncSetAttribute((const void*)k_fused<9, 3, 2>, cudaFuncAttributeMaxDynamicSharedMemorySize, SMEM_BYTES);

    k_prep_w<<<252, 256>>>(prew, c0w, c1w);
    k_cumsum<<<BATCH, NPH>>>(w);
    k_segmean<<<dim3(NPH / SEG_J, BATCH), 256>>>(x);

    dim3 cg(NPH / JT, BATCH);
    k_fused<3, 1, 0><<<cg, 256, SMEM_BYTES>>>(preb, xm, nullptr, nullptr, nullptr, nullptr, 0, nullptr);
    k_fused<9, 3, 1><<<cg, 256, SMEM_BYTES>>>(c0b, xm, g0, b0, nullptr, nullptr, 3 * 12288, nullptr);
    k_fused<9, 3, 2><<<cg, 256, SMEM_BYTES>>>(c1b, xm, g1, b1, lw, lb, 12 * 12288, out);
}

// round 5
// speedup vs baseline: 2.9265x; 1.1215x over previous
#include <cuda_runtime.h>
#include <cuda_bf16.h>
#include <cstdint>

#define BATCH    32
#define CIN      192
#define T_FRAMES 8192
#define H        192
#define NPH      1024
#define NOUT     4
#define EPS      1e-5f

#define JT 128

// ---- smem layout (bytes) ----
// par floats: bias[192], gamma[192], beta[192], linw[768], linb[4] = 1348 -> 5392B
#define SM_BUF0   5504
#define BUF_STRIDE 92160
#define OF_AH 0
#define OF_AL 18432
#define OF_BH 36864
#define OF_BL 64512
#define SMEM_BYTES (SM_BUF0 + 2 * BUF_STRIDE)   // 189824

// ---- device scratch ----
#define PLANE (BATCH * NPH * H)
__device__ __align__(16) int g_ends[BATCH * NPH];
__device__ __align__(16) __nv_bfloat16 g_spec_h[PLANE], g_spec_l[PLANE];
__device__ __align__(16) __nv_bfloat16 g_h0_h[PLANE],   g_h0_l[PLANE];
__device__ __align__(16) __nv_bfloat16 g_a0_h[PLANE],   g_a0_l[PLANE];
#define WTOT (21 * 12288)
__device__ __align__(16) __nv_bfloat16 g_w_h[WTOT], g_w_l[WTOT];

// ===================== helpers =====================
__device__ __forceinline__ uint32_t smem_u32(const void* p) {
    uint32_t a;
    asm("{ .reg .u64 t; cvta.to.shared.u64 t, %1; cvt.u32.u64 %0, t; }" : "=r"(a) : "l"(p));
    return a;
}
__device__ __forceinline__ void cp16(uint32_t dst, const void* src, uint32_t nbytes) {
    asm volatile("cp.async.ca.shared.global [%0], [%1], 16, %2;"
                 :: "r"(dst), "l"(src), "r"(nbytes) : "memory");
}
__device__ __forceinline__ void cp_commit() {
    asm volatile("cp.async.commit_group;" ::: "memory");
}
template <int N>
__device__ __forceinline__ void cp_wait() {
    asm volatile("cp.async.wait_group %0;" :: "n"(N) : "memory");
}
__device__ __forceinline__ void ldsm4(uint32_t* r, uint32_t a) {
    asm volatile("ldmatrix.sync.aligned.m8n8.x4.shared.b16 {%0,%1,%2,%3}, [%4];"
        : "=r"(r[0]), "=r"(r[1]), "=r"(r[2]), "=r"(r[3]) : "r"(a));
}
__device__ __forceinline__ void mma16816(float* d, const uint32_t* a, const uint32_t* bq) {
    asm volatile("mma.sync.aligned.m16n8k16.row.col.f32.bf16.bf16.f32 "
        "{%0,%1,%2,%3}, {%4,%5,%6,%7}, {%8,%9}, {%0,%1,%2,%3};"
        : "+f"(d[0]), "+f"(d[1]), "+f"(d[2]), "+f"(d[3])
        : "r"(a[0]), "r"(a[1]), "r"(a[2]), "r"(a[3]), "r"(bq[0]), "r"(bq[1]));
}
__device__ __forceinline__ uint32_t pack_bf16(float hi_el, float lo_el) {
    uint32_t r;
    asm("cvt.rn.bf16x2.f32 %0, %1, %2;" : "=r"(r) : "f"(hi_el), "f"(lo_el));
    return r;
}

// ===================== 0) weight prep =====================
__global__ void k_prep_w(const float* __restrict__ prew, const float* __restrict__ c0w,
                         const float* __restrict__ c1w) {
    for (int idx = blockIdx.x * blockDim.x + threadIdx.x; idx < WTOT; idx += gridDim.x * blockDim.x) {
        int chunk = idx / 12288, rem = idx % 12288;
        int oc = rem >> 6, i = rem & 63;
        float v;
        if (chunk < 3) {
            v = prew[oc * CIN + chunk * 64 + i];
        } else if (chunk < 12) {
            int cc = chunk - 3, tau = cc / 3, ic = (cc % 3) * 64 + i;
            v = c0w[(oc * H + ic) * 3 + tau];
        } else {
            int cc = chunk - 12, tau = cc / 3, ic = (cc % 3) * 64 + i;
            v = c1w[(oc * H + ic) * 3 + tau];
        }
        __nv_bfloat16 hb = __float2bfloat16(v);
        g_w_h[idx] = hb;
        g_w_l[idx] = __float2bfloat16(v - __bfloat162float(hb));
    }
}

// ===================== 1) per-batch inclusive scan =====================
__global__ void k_cumsum(const int* __restrict__ w) {
    __shared__ int s[NPH];
    int b = blockIdx.x, t = threadIdx.x;
    s[t] = w[b * NPH + t];
    __syncthreads();
    for (int off = 1; off < NPH; off <<= 1) {
        int v = (t >= off) ? s[t - off] : 0;
        __syncthreads();
        s[t] += v;
        __syncthreads();
    }
    g_ends[b * NPH + t] = s[t];
}

// ===================== 2) segment mean -> bf16 hi/lo planes [b][j][c] =====================
#define SEG_J 8
__global__ void k_segmean(const float* __restrict__ x) {
    __shared__ float fr[CIN][SEG_J * 7 + 1];
    __shared__ int se[SEG_J + 1];
    int b = blockIdx.y, j0 = blockIdx.x * SEG_J, tid = threadIdx.x;
    if (tid <= SEG_J) {
        int j = j0 + tid - 1;
        se[tid] = (j >= 0) ? g_ends[b * NPH + j] : 0;
    }
    __syncthreads();
    int t0 = se[0], L = se[SEG_J] - t0;
    const float* xb = x + (size_t)b * CIN * T_FRAMES + t0;
    for (int idx = tid; idx < CIN * L; idx += blockDim.x) {
        int c = idx / L, tt = idx - c * L;
        fr[c][tt] = xb[c * T_FRAMES + tt];
    }
    __syncthreads();
    for (int idx = tid; idx < CIN * SEG_J; idx += blockDim.x) {
        int c = idx >> 3, jj = idx & 7;
        int s = se[jj] - t0, e = se[jj + 1] - t0;
        float acc = 0.f;
        for (int tt = s; tt < e; ++tt) acc += fr[c][tt];
        float v = (e > s) ? acc / (float)(e - s) : 0.f;
        int o = (b * NPH + j0 + jj) * H + c;
        __nv_bfloat16 hb = __float2bfloat16(v);
        g_spec_h[o] = hb;
        g_spec_l[o] = __float2bfloat16(v - __bfloat162float(hb));
    }
}

// ===================== 3) fused HMMA GEMM layer (double-buffered cp.async) =====================
template <int NCHUNKS, int NTAPS, int MODE>
__global__ void __launch_bounds__(256, 1)
k_fused(const float* __restrict__ bias_g, const float* __restrict__ xmask,
        const float* __restrict__ lng, const float* __restrict__ lnb,
        const float* __restrict__ linw, const float* __restrict__ linb,
        int wofs, float* __restrict__ outp) {
    extern __shared__ char smem[];
    const uint32_t sb = smem_u32(smem);
    const int tid  = threadIdx.x;
    const int lane = tid & 31;
    const int wid  = tid >> 5;
    const int wm   = wid >> 2;
    const int wn   = wid & 3;
    const int b    = blockIdx.y;
    const int j0   = blockIdx.x * JT;

    const uint32_t* inH = (const uint32_t*)(MODE == 0 ? g_spec_h : (MODE == 1 ? g_h0_h : g_a0_h));
    const uint32_t* inL = (const uint32_t*)(MODE == 0 ? g_spec_l : (MODE == 1 ? g_h0_l : g_a0_l));
    uint32_t* outH = (uint32_t*)(MODE == 0 ? g_h0_h : g_a0_h);
    uint32_t* outL = (uint32_t*)(MODE == 0 ? g_h0_l : g_a0_l);
    const uint32_t* wH = ((const uint32_t*)g_w_h) + (wofs >> 1);
    const uint32_t* wL = ((const uint32_t*)g_w_l) + (wofs >> 1);

    float* par = (float*)smem;
    for (int i = tid; i < H; i += 256) par[i] = bias_g[i];
    if (MODE != 0)
        for (int i = tid; i < H; i += 256) { par[192 + i] = lng[i]; par[384 + i] = lnb[i]; }
    if (MODE == 2) {
        for (int i = tid; i < NOUT * H; i += 256) par[576 + i] = linw[i];
        if (tid < NOUT) par[1344 + tid] = linb[tid];
    }

    // ---- cp.async stage of one K-64 chunk into buffer bi ----
    auto stage = [&](int c, int bi) {
        const int tau = (NTAPS == 3) ? c / 3 : 0;
        const int icb = (NTAPS == 3) ? c % 3 : c;
        const uint32_t bufb = sb + SM_BUF0 + bi * BUF_STRIDE;
        // A: 128 rows x 8 x 16B per plane
#pragma unroll
        for (int i = 0; i < 4; i++) {
            int idx = tid + i * 256;
            int row = idx >> 3, seg = idx & 7;
            int jr = j0 + row + ((NTAPS == 3) ? tau - 1 : 0);
            uint32_t ok = ((unsigned)jr < NPH) ? 16u : 0u;
            int jrc = (jr < 0) ? 0 : (jr >= NPH ? NPH - 1 : jr);
            int s = (b * NPH + jrc) * 96 + icb * 32 + seg * 4;
            uint32_t d = (uint32_t)(row * 144 + seg * 16);
            cp16(bufb + OF_AH + d, inH + s, ok);
            cp16(bufb + OF_AL + d, inL + s, ok);
        }
        // B: 192 rows x 8 x 16B per plane (contiguous)
#pragma unroll
        for (int i = 0; i < 6; i++) {
            int idx = tid + i * 256;
            int row = idx >> 3, seg = idx & 7;
            int s = c * 6144 + idx * 4;
            uint32_t d = (uint32_t)(row * 144 + seg * 16);
            cp16(bufb + OF_BH + d, wH + s, 16u);
            cp16(bufb + OF_BL + d, wL + s, 16u);
        }
        cp_commit();
    };

    float acc[4][6][4];
#pragma unroll
    for (int mt = 0; mt < 4; mt++)
#pragma unroll
        for (int nt = 0; nt < 6; nt++)
#pragma unroll
            for (int q = 0; q < 4; q++) acc[mt][nt][q] = 0.f;

    stage(0, 0);

#pragma unroll 1
    for (int c = 0; c < NCHUNKS; c++) {
        __syncthreads();                       // buffer (c+1)&1 free (mma of c-1 done)
        if (c + 1 < NCHUNKS) stage(c + 1, (c + 1) & 1);
        if (c + 1 < NCHUNKS) cp_wait<1>(); else cp_wait<0>();
        __syncthreads();                       // chunk c visible to all warps
        const uint32_t bufb = sb + SM_BUF0 + (c & 1) * BUF_STRIDE;

#pragma unroll 1
        for (int ks = 0; ks < 4; ks++) {
            uint32_t ah[4][4], al[4][4], bh[6][2], bl[6][2];
            {
                int t = lane >> 3, r = lane & 7;
                int rowA = 64 * wm + r + ((t & 1) << 3);
                int colA = (ks << 4) + ((t & 2) << 2);
                uint32_t aoff = (uint32_t)(rowA * 144 + colA * 2);
#pragma unroll
                for (int mt = 0; mt < 4; mt++) {
                    ldsm4(ah[mt], bufb + OF_AH + aoff + mt * (16 * 144));
                    ldsm4(al[mt], bufb + OF_AL + aoff + mt * (16 * 144));
                }
                // B: ldmatrix.x4 over nt pairs
                int g = lane >> 3, rr = lane & 7;
                int rowBb = 48 * wn + ((g >> 1) << 3) + rr;
                int colB = (ks << 4) + ((g & 1) << 3);
                uint32_t boff0 = (uint32_t)(rowBb * 144 + colB * 2);
#pragma unroll
                for (int p = 0; p < 3; p++) {
                    uint32_t tmp[4];
                    ldsm4(tmp, bufb + OF_BH + boff0 + p * (16 * 144));
                    bh[2 * p][0] = tmp[0]; bh[2 * p][1] = tmp[1];
                    bh[2 * p + 1][0] = tmp[2]; bh[2 * p + 1][1] = tmp[3];
                    ldsm4(tmp, bufb + OF_BL + boff0 + p * (16 * 144));
                    bl[2 * p][0] = tmp[0]; bl[2 * p][1] = tmp[1];
                    bl[2 * p + 1][0] = tmp[2]; bl[2 * p + 1][1] = tmp[3];
                }
            }
#pragma unroll
            for (int mt = 0; mt < 4; mt++)
#pragma unroll
                for (int nt = 0; nt < 6; nt++) {
                    mma16816(acc[mt][nt], ah[mt], bh[nt]);
                    mma16816(acc[mt][nt], ah[mt], bl[nt]);
                    mma16816(acc[mt][nt], al[mt], bh[nt]);
                }
        }
    }
    __syncthreads();   // stage smem dead; safe to overlay reductions

    if (MODE == 0) {
#pragma unroll
        for (int mt = 0; mt < 4; mt++)
#pragma unroll
            for (int t = 0; t < 2; t++) {
                int jloc = 64 * wm + 16 * mt + (lane >> 2) + 8 * t;
                int j = j0 + jloc;
                float m = xmask[b * NPH + j];
                uint32_t* oH = outH + (b * NPH + j) * 96;
                uint32_t* oL = outL + (b * NPH + j) * 96;
#pragma unroll
                for (int nt = 0; nt < 6; nt++) {
                    int c0 = 48 * wn + 8 * nt + (lane & 3) * 2;
                    float v0 = (acc[mt][nt][2 * t + 0] + par[c0])     * m;
                    float v1 = (acc[mt][nt][2 * t + 1] + par[c0 + 1]) * m;
                    uint32_t ph = pack_bf16(v1, v0);
                    float f0 = __uint_as_float(ph << 16), f1 = __uint_as_float(ph & 0xffff0000u);
                    uint32_t pl = pack_bf16(v1 - f1, v0 - f0);
                    oH[c0 >> 1] = ph; oL[c0 >> 1] = pl;
                }
            }
        return;
    }

    float* redS1 = (float*)(smem + SM_BUF0);        // [128][4]
    float* redS2 = redS1 + 512;                     // [128][4]
    float* redLin = redS2 + 512;                    // [4][128][4]

#pragma unroll
    for (int mt = 0; mt < 4; mt++)
#pragma unroll
        for (int t = 0; t < 2; t++) {
            int jloc = 64 * wm + 16 * mt + (lane >> 2) + 8 * t;
            float m = xmask[b * NPH + j0 + jloc];
            float s1 = 0.f, s2 = 0.f;
#pragma unroll
            for (int nt = 0; nt < 6; nt++) {
                int c0 = 48 * wn + 8 * nt + (lane & 3) * 2;
#pragma unroll
                for (int q = 0; q < 2; q++) {
                    float v = fmaxf((acc[mt][nt][2 * t + q] + par[c0 + q]) * m, 0.f) * m;
                    s1 += v; s2 += v * v;
                }
            }
            s1 += __shfl_xor_sync(0xffffffffu, s1, 1); s1 += __shfl_xor_sync(0xffffffffu, s1, 2);
            s2 += __shfl_xor_sync(0xffffffffu, s2, 1); s2 += __shfl_xor_sync(0xffffffffu, s2, 2);
            if ((lane & 3) == 0) { redS1[jloc * 4 + wn] = s1; redS2[jloc * 4 + wn] = s2; }
        }
    __syncthreads();

#pragma unroll
    for (int mt = 0; mt < 4; mt++)
#pragma unroll
        for (int t = 0; t < 2; t++) {
            int jloc = 64 * wm + 16 * mt + (lane >> 2) + 8 * t;
            int j = j0 + jloc;
            float m = xmask[b * NPH + j];
            float s1 = redS1[jloc * 4 + 0] + redS1[jloc * 4 + 1] + redS1[jloc * 4 + 2] + redS1[jloc * 4 + 3];
            float s2 = redS2[jloc * 4 + 0] + redS2[jloc * 4 + 1] + redS2[jloc * 4 + 2] + redS2[jloc * 4 + 3];
            float mean = s1 * (1.f / H);
            float rstd = rsqrtf(s2 * (1.f / H) - mean * mean + EPS);
            if (MODE == 1) {
                uint32_t* oH = outH + (b * NPH + j) * 96;
                uint32_t* oL = outL + (b * NPH + j) * 96;
#pragma unroll
                for (int nt = 0; nt < 6; nt++) {
                    int c0 = 48 * wn + 8 * nt + (lane & 3) * 2;
                    float v0 = fmaxf((acc[mt][nt][2 * t + 0] + par[c0])     * m, 0.f) * m;
                    float v1 = fmaxf((acc[mt][nt][2 * t + 1] + par[c0 + 1]) * m, 0.f) * m;
                    float y0 = ((v0 - mean) * rstd * par[192 + c0]     + par[384 + c0])     * m * m;
                    float y1 = ((v1 - mean) * rstd * par[192 + c0 + 1] + par[384 + c0 + 1]) * m * m;
                    uint32_t ph = pack_bf16(y1, y0);
                    float f0 = __uint_as_float(ph << 16), f1 = __uint_as_float(ph & 0xffff0000u);
                    uint32_t pl = pack_bf16(y1 - f1, y0 - f0);
                    oH[c0 >> 1] = ph; oL[c0 >> 1] = pl;
                }
            } else {
                float p0 = 0.f, p1 = 0.f, p2 = 0.f, p3 = 0.f;
#pragma unroll
                for (int nt = 0; nt < 6; nt++) {
                    int c0 = 48 * wn + 8 * nt + (lane & 3) * 2;
#pragma unroll
                    for (int q = 0; q < 2; q++) {
                        int cc = c0 + q;
                        float v = fmaxf((acc[mt][nt][2 * t + q] + par[cc]) * m, 0.f) * m;
                        float y = ((v - mean) * rstd * par[192 + cc] + par[384 + cc]) * m;
                        p0 += y * par[576 + 0 * H + cc];
                        p1 += y * par[576 + 1 * H + cc];
                        p2 += y * par[576 + 2 * H + cc];
                        p3 += y * par[576 + 3 * H + cc];
                    }
                }
                p0 += __shfl_xor_sync(0xffffffffu, p0, 1); p0 += __shfl_xor_sync(0xffffffffu, p0, 2);
                p1 += __shfl_xor_sync(0xffffffffu, p1, 1); p1 += __shfl_xor_sync(0xffffffffu, p1, 2);
                p2 += __shfl_xor_sync(0xffffffffu, p2, 1); p2 += __shfl_xor_sync(0xffffffffu, p2, 2);
                p3 += __shfl_xor_sync(0xffffffffu, p3, 1); p3 += __shfl_xor_sync(0xffffffffu, p3, 2);
                if ((lane & 3) == 0) {
                    redLin[(0 * 128 + jloc) * 4 + wn] = p0;
                    redLin[(1 * 128 + jloc) * 4 + wn] = p1;
                    redLin[(2 * 128 + jloc) * 4 + wn] = p2;
                    redLin[(3 * 128 + jloc) * 4 + wn] = p3;
                }
            }
        }

    if (MODE == 2) {
        __syncthreads();
        for (int oj = tid; oj < 512; oj += 256) {
            int o = oj >> 7, jl = oj & 127;
            float s = redLin[(o * 128 + jl) * 4 + 0] + redLin[(o * 128 + jl) * 4 + 1]
                    + redLin[(o * 128 + jl) * 4 + 2] + redLin[(o * 128 + jl) * 4 + 3];
            s += par[1344 + o];
            s *= xmask[b * NPH + j0 + jl];
            outp[(b * NOUT + o) * NPH + j0 + jl] = s;
        }
    }
}

// ===================== launch =====================
extern "C" void kernel_launch(void* const* d_in, const int* in_sizes, int n_in,
                              void* d_out, int out_size) {
    (void)in_sizes; (void)n_in; (void)out_size;
    const float* x    = (const float*)d_in[0];
    const float* xm   = (const float*)d_in[1];
    const int*   w    = (const int*)d_in[2];
    const float* prew = (const float*)d_in[3];
    const float* preb = (const float*)d_in[4];
    const float* c0w  = (const float*)d_in[5];
    const float* c0b  = (const float*)d_in[6];
    const float* g0   = (const float*)d_in[7];
    const float* b0   = (const float*)d_in[8];
    const float* c1w  = (const float*)d_in[9];
    const float* c1b  = (const float*)d_in[10];
    const float* g1   = (const float*)d_in[11];
    const float* b1   = (const float*)d_in[12];
    const float* lw   = (const float*)d_in[13];
    const float* lb   = (const float*)d_in[14];
    float* out = (float*)d_out;

    cudaFuncSetAttribute((const void*)k_fused<3, 1, 0>, cudaFuncAttributeMaxDynamicSharedMemorySize, SMEM_BYTES);
    cudaFuncSetAttribute((const void*)k_fused<9, 3, 1>, cudaFuncAttributeMaxDynamicSharedMemorySize, SMEM_BYTES);
    cudaFuncSetAttribute((const void*)k_fused<9, 3, 2>, cudaFuncAttributeMaxDynamicSharedMemorySize, SMEM_BYTES);

    k_prep_w<<<252, 256>>>(prew, c0w, c1w);
    k_cumsum<<<BATCH, NPH>>>(w);
    k_segmean<<<dim3(NPH / SEG_J, BATCH), 256>>>(x);

    dim3 cg(NPH / JT, BATCH);
    k_fused<3, 1, 0><<<cg, 256, SMEM_BYTES>>>(preb, xm, nullptr, nullptr, nullptr, nullptr, 0, nullptr);
    k_fused<9, 3, 1><<<cg, 256, SMEM_BYTES>>>(c0b, xm, g0, b0, nullptr, nullptr, 3 * 12288, nullptr);
    k_fused<9, 3, 2><<<cg, 256, SMEM_BYTES>>>(c1b, xm, g1, b1, lw, lb, 12 * 12288, out);
}